// round 1
// baseline (speedup 1.0000x reference)
#include <cuda_runtime.h>
#include <cstdint>

#define B_    64
#define P_    49
#define ENC_  1280
#define T_    25
#define V_    10000
#define E_    512
#define H_    1024
#define A_    512
#define GIN_K (E_ + ENC_ + H_)   /* 2816 */
#define K1SP  (E_ + ENC_)        /* 1792 */

// ---------------- scratch (static device memory; no allocs) ----------------
__device__ __align__(16) float g_mean[B_ * ENC_];
__device__ __align__(16) float g_h[2 * B_ * H_];
__device__ __align__(16) float g_c[2 * B_ * H_];
__device__ __align__(16) float g_att1[B_ * P_ * A_];
__device__ __align__(16) float g_att2p[4 * B_ * A_];
__device__ __align__(16) float g_gin[B_ * GIN_K];
__device__ __align__(16) float g_gatesp[4 * B_ * 4 * H_];

// ---------------- helpers ----------------
__device__ __forceinline__ uint32_t f2tf(float x) {
    uint32_t r;
    asm("cvt.rna.tf32.f32 %0, %1;" : "=r"(r) : "f"(x));
    return r;
}

// ---------------- mean over P ----------------
__global__ void mean_kernel(const float* __restrict__ enc) {
    int i = blockIdx.x * blockDim.x + threadIdx.x;
    if (i >= B_ * ENC_) return;
    int b = i / ENC_, e = i % ENC_;
    const float* p = enc + (size_t)b * P_ * ENC_ + e;
    float s = 0.f;
#pragma unroll 7
    for (int k = 0; k < P_; k++) s += p[k * ENC_];
    g_mean[i] = s * (1.0f / P_);
}

// ---------------- generic tf32 GEMM: C[M,N] = A[M,K] @ B[N,K]^T (+bias) ----
// Block tile 64x64, BK=32, 4 warps (2x2), warp tile 32x32, m16n8k8 tf32 mma.
// Dual-B source (switch at k1split) for the fused [x,ctx | h] x [W_ih | W_hh].
// Split-K via blockIdx.z -> partial buffers at C + z*partStride (bias only if set).
__global__ void __launch_bounds__(128)
gemm_tf32(const float* __restrict__ A, int lda,
          const float* __restrict__ B1, int ldb1,
          const float* __restrict__ B2, int ldb2, int k1split,
          const float* __restrict__ bias,
          float* __restrict__ C, int ldc, int partStride,
          int N, int K, int kChunk)
{
    __shared__ uint32_t As[64 * 36];
    __shared__ uint32_t Bs[64 * 36];

    const int tid  = threadIdx.x;
    const int warp = tid >> 5, lane = tid & 31;
    const int wm = warp >> 1, wn = warp & 1;
    const int bm = blockIdx.x * 64;
    const int bn = blockIdx.y * 64;
    const int z  = blockIdx.z;
    const int k0 = z * kChunk;
    const int kend = min(k0 + kChunk, K);
    float* Cz = C + (size_t)z * partStride;

    float acc[2][4][4];
#pragma unroll
    for (int i = 0; i < 2; i++)
#pragma unroll
        for (int j = 0; j < 4; j++)
#pragma unroll
            for (int q = 0; q < 4; q++) acc[i][j][q] = 0.f;

    const int lrow = tid >> 3;        // 0..15
    const int lcol = (tid & 7) * 4;   // 0,4,...,28

    float4 ra[4], rb[4];
    // prefetch tile 0
    {
        const float* Bsrc; int ldb, kb;
        if (k0 < k1split) { Bsrc = B1; ldb = ldb1; kb = k0; }
        else              { Bsrc = B2; ldb = ldb2; kb = k0 - k1split; }
#pragma unroll
        for (int i = 0; i < 4; i++) {
            int r = lrow + i * 16;
            ra[i] = *reinterpret_cast<const float4*>(A + (size_t)(bm + r) * lda + k0 + lcol);
            int n = bn + r;
            rb[i] = (n < N) ? *reinterpret_cast<const float4*>(Bsrc + (size_t)n * ldb + kb + lcol)
                            : make_float4(0.f, 0.f, 0.f, 0.f);
        }
    }

    for (int kt = k0; kt < kend; kt += 32) {
        // regs -> smem (tf32 rounded)
#pragma unroll
        for (int i = 0; i < 4; i++) {
            int r = lrow + i * 16;
            uint32_t* pa = &As[r * 36 + lcol];
            pa[0] = f2tf(ra[i].x); pa[1] = f2tf(ra[i].y);
            pa[2] = f2tf(ra[i].z); pa[3] = f2tf(ra[i].w);
            uint32_t* pb = &Bs[r * 36 + lcol];
            pb[0] = f2tf(rb[i].x); pb[1] = f2tf(rb[i].y);
            pb[2] = f2tf(rb[i].z); pb[3] = f2tf(rb[i].w);
        }
        __syncthreads();

        // prefetch next tile
        int ktn = kt + 32;
        if (ktn < kend) {
            const float* Bsrc; int ldb, kb;
            if (ktn < k1split) { Bsrc = B1; ldb = ldb1; kb = ktn; }
            else               { Bsrc = B2; ldb = ldb2; kb = ktn - k1split; }
#pragma unroll
            for (int i = 0; i < 4; i++) {
                int r = lrow + i * 16;
                ra[i] = *reinterpret_cast<const float4*>(A + (size_t)(bm + r) * lda + ktn + lcol);
                int n = bn + r;
                rb[i] = (n < N) ? *reinterpret_cast<const float4*>(Bsrc + (size_t)n * ldb + kb + lcol)
                                : make_float4(0.f, 0.f, 0.f, 0.f);
            }
        }

        // compute on current smem tile
#pragma unroll
        for (int kk = 0; kk < 4; kk++) {
            uint32_t afr[2][4], bfr[4][2];
            const int c = kk * 8 + (lane & 3);
#pragma unroll
            for (int mt = 0; mt < 2; mt++) {
                int r = wm * 32 + mt * 16 + (lane >> 2);
                afr[mt][0] = As[r * 36 + c];
                afr[mt][1] = As[(r + 8) * 36 + c];
                afr[mt][2] = As[r * 36 + c + 4];
                afr[mt][3] = As[(r + 8) * 36 + c + 4];
            }
#pragma unroll
            for (int nt = 0; nt < 4; nt++) {
                int n = wn * 32 + nt * 8 + (lane >> 2);
                bfr[nt][0] = Bs[n * 36 + c];
                bfr[nt][1] = Bs[n * 36 + c + 4];
            }
#pragma unroll
            for (int mt = 0; mt < 2; mt++)
#pragma unroll
                for (int nt = 0; nt < 4; nt++)
                    asm volatile(
                        "mma.sync.aligned.m16n8k8.row.col.f32.tf32.tf32.f32 "
                        "{%0,%1,%2,%3}, {%4,%5,%6,%7}, {%8,%9}, {%0,%1,%2,%3};"
                        : "+f"(acc[mt][nt][0]), "+f"(acc[mt][nt][1]),
                          "+f"(acc[mt][nt][2]), "+f"(acc[mt][nt][3])
                        : "r"(afr[mt][0]), "r"(afr[mt][1]), "r"(afr[mt][2]), "r"(afr[mt][3]),
                          "r"(bfr[nt][0]), "r"(bfr[nt][1]));
        }
        __syncthreads();
    }

    // epilogue
#pragma unroll
    for (int mt = 0; mt < 2; mt++) {
        int r0 = bm + wm * 32 + mt * 16 + (lane >> 2);
#pragma unroll
        for (int nt = 0; nt < 4; nt++) {
            int cg = bn + wn * 32 + nt * 8 + (lane & 3) * 2;
            float bv0 = 0.f, bv1 = 0.f;
            if (bias) {
                if (cg < N) bv0 = bias[cg];
                if (cg + 1 < N) bv1 = bias[cg + 1];
            }
            if (cg < N) {
                Cz[(size_t)r0 * ldc + cg]       = acc[mt][nt][0] + bv0;
                Cz[(size_t)(r0 + 8) * ldc + cg] = acc[mt][nt][2] + bv0;
            }
            if (cg + 1 < N) {
                Cz[(size_t)r0 * ldc + cg + 1]       = acc[mt][nt][1] + bv1;
                Cz[(size_t)(r0 + 8) * ldc + cg + 1] = acc[mt][nt][3] + bv1;
            }
        }
    }
}

// ---------------- attention + gin assembly (one block per batch b) ---------
// Reduces att2 split-K partials, computes e/softmax/ctx, gathers x_t embed,
// and packs gin = [x_t | ctx | h_prev].
__global__ void __launch_bounds__(256)
attn_kernel(const float* __restrict__ enc,
            const int* __restrict__ captions,
            const float* __restrict__ embed,
            const float* __restrict__ b_datt,
            const float* __restrict__ W_fatt,
            const float* __restrict__ b_fatt,
            const float* __restrict__ hprev,
            int t)
{
    int b = blockIdx.x;
    int tid = threadIdx.x;
    int warp = tid >> 5, lane = tid & 31;

    __shared__ float att2s[A_];
    __shared__ float es[P_];

    for (int a = tid; a < A_; a += 256) {
        float s = b_datt[a];
#pragma unroll
        for (int zz = 0; zz < 4; zz++) s += g_att2p[zz * B_ * A_ + b * A_ + a];
        att2s[a] = s;
    }
    __syncthreads();

    const float* att1b = g_att1 + (size_t)b * P_ * A_;
    for (int p = warp; p < P_; p += 8) {
        float s = 0.f;
        for (int a = lane; a < A_; a += 32) {
            float v = att1b[p * A_ + a] + att2s[a];
            s += fmaxf(v, 0.f) * W_fatt[a];
        }
#pragma unroll
        for (int o = 16; o; o >>= 1) s += __shfl_xor_sync(0xffffffffu, s, o);
        if (lane == 0) es[p] = s + b_fatt[0];
    }
    __syncthreads();

    if (warp == 0) {
        float v0 = (lane < P_) ? es[lane] : -1e30f;
        float v1 = (lane + 32 < P_) ? es[lane + 32] : -1e30f;
        float m = fmaxf(v0, v1);
#pragma unroll
        for (int o = 16; o; o >>= 1) m = fmaxf(m, __shfl_xor_sync(0xffffffffu, m, o));
        float e0 = (lane < P_) ? __expf(v0 - m) : 0.f;
        float e1 = (lane + 32 < P_) ? __expf(v1 - m) : 0.f;
        float s = e0 + e1;
#pragma unroll
        for (int o = 16; o; o >>= 1) s += __shfl_xor_sync(0xffffffffu, s, o);
        float inv = 1.0f / s;
        if (lane < P_) es[lane] = e0 * inv;
        if (lane + 32 < P_) es[lane + 32] = e1 * inv;
    }
    __syncthreads();

    float* gin = g_gin + (size_t)b * GIN_K;
    int cap = captions[b * T_ + t];
    const float* erow = embed + (size_t)cap * E_;
    for (int i = tid; i < E_; i += 256) gin[i] = erow[i];

    const float* encb = enc + (size_t)b * P_ * ENC_;
    for (int e = tid; e < ENC_; e += 256) {
        float s = 0.f;
#pragma unroll 7
        for (int p = 0; p < P_; p++) s += es[p] * encb[p * ENC_ + e];
        gin[E_ + e] = s;
    }
    for (int j = tid; j < H_; j += 256) gin[K1SP + j] = hprev[b * H_ + j];
}

// ---------------- LSTM pointwise (reduces gates split-K partials) -----------
__global__ void __launch_bounds__(256)
lstm_kernel(const float* __restrict__ b_ih, const float* __restrict__ b_hh,
            const float* __restrict__ cprev,
            float* __restrict__ hnew, float* __restrict__ cnew)
{
    int i = blockIdx.x * blockDim.x + threadIdx.x;
    if (i >= B_ * H_) return;
    int b = i / H_, j = i % H_;
    size_t base = (size_t)b * 4 * H_ + j;
    float gi = 0.f, gf = 0.f, gg = 0.f, go = 0.f;
#pragma unroll
    for (int zz = 0; zz < 4; zz++) {
        const float* gp = g_gatesp + (size_t)zz * B_ * 4 * H_ + base;
        gi += gp[0]; gf += gp[H_]; gg += gp[2 * H_]; go += gp[3 * H_];
    }
    gi += b_ih[j]          + b_hh[j];
    gf += b_ih[H_ + j]     + b_hh[H_ + j];
    gg += b_ih[2 * H_ + j] + b_hh[2 * H_ + j];
    go += b_ih[3 * H_ + j] + b_hh[3 * H_ + j];
    float si = 1.f / (1.f + __expf(-gi));
    float sf = 1.f / (1.f + __expf(-gf));
    float so = 1.f / (1.f + __expf(-go));
    float tg = tanhf(gg);
    float c  = sf * cprev[i] + si * tg;
    cnew[i] = c;
    hnew[i] = so * tanhf(c);
}

// ---------------- host ----------------
static float* sym_addr(const void* sym) {
    void* p = nullptr;
    cudaGetSymbolAddress(&p, sym);
    return (float*)p;
}

extern "C" void kernel_launch(void* const* d_in, const int* in_sizes, int n_in,
                              void* d_out, int out_size)
{
    const float* enc    = (const float*)d_in[0];
    const int*   caps   = (const int*)  d_in[1];
    const float* embed  = (const float*)d_in[2];
    const float* W_eatt = (const float*)d_in[3];
    const float* b_eatt = (const float*)d_in[4];
    const float* W_datt = (const float*)d_in[5];
    const float* b_datt = (const float*)d_in[6];
    const float* W_fatt = (const float*)d_in[7];
    const float* b_fatt = (const float*)d_in[8];
    const float* W_ih   = (const float*)d_in[9];
    const float* b_ih   = (const float*)d_in[10];
    const float* W_hh   = (const float*)d_in[11];
    const float* b_hh   = (const float*)d_in[12];
    const float* W_h0   = (const float*)d_in[13];
    const float* b_h0   = (const float*)d_in[14];
    const float* W_c0   = (const float*)d_in[15];
    const float* b_c0   = (const float*)d_in[16];
    const float* W_out  = (const float*)d_in[17];
    const float* b_out  = (const float*)d_in[18];
    float* out = (float*)d_out;

    float* mean   = sym_addr(g_mean);
    float* hbuf   = sym_addr(g_h);
    float* cbuf   = sym_addr(g_c);
    float* att1   = sym_addr(g_att1);
    float* att2p  = sym_addr(g_att2p);
    float* gin    = sym_addr(g_gin);
    float* gatesp = sym_addr(g_gatesp);

    const int BH = B_ * H_;

    // setup: mean, h0, c0, att1
    mean_kernel<<<(B_ * ENC_ + 255) / 256, 256>>>(enc);
    gemm_tf32<<<dim3(1, H_ / 64, 1), 128>>>(mean, ENC_, W_h0, ENC_, W_h0, ENC_, 1 << 30,
                                            b_h0, hbuf, H_, 0, H_, ENC_, ENC_);
    gemm_tf32<<<dim3(1, H_ / 64, 1), 128>>>(mean, ENC_, W_c0, ENC_, W_c0, ENC_, 1 << 30,
                                            b_c0, cbuf, H_, 0, H_, ENC_, ENC_);
    gemm_tf32<<<dim3((B_ * P_) / 64, A_ / 64, 1), 128>>>(enc, ENC_, W_eatt, ENC_, W_eatt, ENC_, 1 << 30,
                                                         b_eatt, att1, A_, 0, A_, ENC_, ENC_);

    for (int t = 0; t < T_ - 1; t++) {
        float* h_cur = hbuf + (t & 1) * BH;
        float* c_cur = cbuf + (t & 1) * BH;
        float* h_nxt = hbuf + ((t + 1) & 1) * BH;
        float* c_nxt = cbuf + ((t + 1) & 1) * BH;

        // att2 = h @ W_datt^T  (split-K 4, partials)
        gemm_tf32<<<dim3(1, A_ / 64, 4), 128>>>(h_cur, H_, W_datt, H_, W_datt, H_, 1 << 30,
                                                nullptr, att2p, A_, B_ * A_, A_, H_, H_ / 4);

        // attention + gin = [x_t | ctx | h]
        attn_kernel<<<B_, 256>>>(enc, caps, embed, b_datt, W_fatt, b_fatt, h_cur, t);

        // gates = gin @ [W_ih | W_hh]^T  (split-K 4, partials)
        gemm_tf32<<<dim3(1, (4 * H_) / 64, 4), 128>>>(gin, GIN_K, W_ih, K1SP, W_hh, H_, K1SP,
                                                      nullptr, gatesp, 4 * H_, B_ * 4 * H_,
                                                      4 * H_, GIN_K, GIN_K / 4);

        // LSTM pointwise
        lstm_kernel<<<(B_ * H_ + 255) / 256, 256>>>(b_ih, b_hh, c_cur, h_nxt, c_nxt);

        // preds = h_new @ W_out^T + b_out -> out[:, t, :]
        gemm_tf32<<<dim3(1, (V_ + 63) / 64, 1), 128>>>(h_nxt, H_, W_out, H_, W_out, H_, 1 << 30,
                                                       b_out, out + (size_t)t * V_,
                                                       (T_ - 1) * V_, 0, V_, H_, H_);
    }
}

// round 2
// speedup vs baseline: 2.0120x; 2.0120x over previous
#include <cuda_runtime.h>
#include <cuda_fp16.h>
#include <cstdint>

#define B_    64
#define P_    49
#define ENC_  1280
#define T_    25
#define V_    10000
#define E_    512
#define H_    1024
#define A_    512
#define GK_   2816   /* E + ENC + H */
#define K1_   1792   /* E + ENC */

#define BM 64
#define BN 64
#define BK 64
#define STG 3
#define RS 72        /* smem row stride in halves (64 + 8 pad, 16B aligned) */
#define SMEM_BYTES (STG * (BM + BN) * RS * 2)

// ---------------- static scratch (no allocs) ----------------
__device__ __align__(16) __half g_Wout [V_ * H_];
__device__ __align__(16) __half g_Wg   [4 * H_ * GK_];
__device__ __align__(16) __half g_Wdatt[A_ * H_];
__device__ __align__(16) __half g_Weatt[A_ * ENC_];
__device__ __align__(16) __half g_Wh0  [H_ * ENC_];
__device__ __align__(16) __half g_Wc0  [H_ * ENC_];
__device__ __align__(16) __half g_ench [B_ * P_ * ENC_];
__device__ __align__(16) __half g_embh [V_ * E_];
__device__ __align__(16) __half g_meanh[B_ * ENC_];
__device__ __align__(16) __half g_hbuf [2 * B_ * H_];
__device__ __align__(16) __half g_gin  [B_ * GK_];
__device__ __align__(16) float  g_cbuf [2 * B_ * H_];
__device__ __align__(16) float  g_att1 [B_ * P_ * A_];
__device__ __align__(16) float  g_att2p[8 * B_ * A_];
__device__ __align__(16) float  g_gatesp[2 * B_ * 4 * H_];

// ---------------- setup: convert everything to fp16 ----------------
// segments (cumulative):
#define S0 (A_ * H_)                    /* W_datt   */
#define S1 (S0 + V_ * H_)               /* W_out    */
#define S2 (S1 + A_ * ENC_)             /* W_eatt   */
#define S3 (S2 + H_ * ENC_)             /* W_h0     */
#define S4 (S3 + H_ * ENC_)             /* W_c0     */
#define S5 (S4 + B_ * P_ * ENC_)        /* enc      */
#define S6 (S5 + V_ * E_)               /* embed    */
#define S7 (S6 + 4 * H_ * K1_)          /* W_ih -> Wg[:, 0:1792]   */
#define S8 (S7 + 4 * H_ * H_)           /* W_hh -> Wg[:, 1792:]    */

__global__ void cvt_all(const float* __restrict__ Wd, const float* __restrict__ Wo,
                        const float* __restrict__ We, const float* __restrict__ Wh0,
                        const float* __restrict__ Wc0, const float* __restrict__ enc,
                        const float* __restrict__ emb, const float* __restrict__ Wih,
                        const float* __restrict__ Whh)
{
    int i = blockIdx.x * 256 + threadIdx.x;
    if (i >= S8) return;
    if (i < S0)      g_Wdatt[i]      = __float2half(Wd[i]);
    else if (i < S1) g_Wout[i - S0]  = __float2half(Wo[i - S0]);
    else if (i < S2) g_Weatt[i - S1] = __float2half(We[i - S1]);
    else if (i < S3) g_Wh0[i - S2]   = __float2half(Wh0[i - S2]);
    else if (i < S4) g_Wc0[i - S3]   = __float2half(Wc0[i - S3]);
    else if (i < S5) g_ench[i - S4]  = __float2half(enc[i - S4]);
    else if (i < S6) g_embh[i - S5]  = __float2half(emb[i - S5]);
    else if (i < S7) {
        int j = i - S6; int r = j / K1_, c = j % K1_;
        g_Wg[(size_t)r * GK_ + c] = __float2half(Wih[j]);
    } else {
        int j = i - S7; int r = j / H_, c = j % H_;
        g_Wg[(size_t)r * GK_ + K1_ + c] = __float2half(Whh[j]);
    }
}

// ---------------- mean over P (write fp16) ----------------
__global__ void mean_kernel(const float* __restrict__ enc) {
    int i = blockIdx.x * blockDim.x + threadIdx.x;
    if (i >= B_ * ENC_) return;
    int b = i / ENC_, e = i % ENC_;
    const float* p = enc + (size_t)b * P_ * ENC_ + e;
    float s = 0.f;
#pragma unroll 7
    for (int k = 0; k < P_; k++) s += p[k * ENC_];
    g_meanh[i] = __float2half(s * (1.0f / P_));
}

// ---------------- fp16 GEMM: C[M,N] = A[M,K] @ B[N,K]^T (+bias) -----------
// 64x64 block tile, BK=64, 4 warps (2x2), warp tile 32x32, m16n8k16 f16 mma,
// 3-stage cp.async pipeline. Split-K via blockIdx.z -> partials (no bias).
__device__ __forceinline__ void issue_tile(
    const __half* __restrict__ A, int lda,
    const __half* __restrict__ B, int ldb,
    int bm, int bn, int N, int kt,
    __half* as, __half* bs, int tid)
{
#pragma unroll
    for (int i = 0; i < 4; i++) {
        int idx = i * 128 + tid;
        int r = idx >> 3, c8 = (idx & 7) * 8;
        uint32_t da = (uint32_t)__cvta_generic_to_shared(as + r * RS + c8);
        const __half* pa = A + (size_t)(bm + r) * lda + kt + c8;
        asm volatile("cp.async.cg.shared.global [%0], [%1], 16;" :: "r"(da), "l"(pa));
        int n = bn + r;
        uint32_t db = (uint32_t)__cvta_generic_to_shared(bs + r * RS + c8);
        const __half* pb = B + (size_t)(n < N ? n : 0) * ldb + kt + c8;
        int sz = (n < N) ? 16 : 0;
        asm volatile("cp.async.cg.shared.global [%0], [%1], 16, %2;" :: "r"(db), "l"(pb), "r"(sz));
    }
    asm volatile("cp.async.commit_group;");
}

__global__ void __launch_bounds__(128)
hgemm(const __half* __restrict__ A, int lda,
      const __half* __restrict__ Bm, int ldb,
      const float* __restrict__ bias,
      float* __restrict__ Cf, __half* __restrict__ Ch,
      int ldc, int partStride, int N, int kChunk)
{
    extern __shared__ __half sm[];
    __half* Asm = sm;
    __half* Bsm = sm + STG * BM * RS;

    const int tid = threadIdx.x;
    const int warp = tid >> 5, lane = tid & 31;
    const int wm = warp >> 1, wn = warp & 1;
    const int bm = blockIdx.x * BM, bn = blockIdx.y * BN;
    const int z = blockIdx.z;
    const int k0 = z * kChunk;
    const int nk = kChunk / BK;

    float acc[2][4][4];
#pragma unroll
    for (int i = 0; i < 2; i++)
#pragma unroll
        for (int j = 0; j < 4; j++)
#pragma unroll
            for (int q = 0; q < 4; q++) acc[i][j][q] = 0.f;

    // prologue: preload STG-1 tiles
#pragma unroll
    for (int s = 0; s < STG - 1; s++) {
        if (s < nk) issue_tile(A, lda, Bm, ldb, bm, bn, N, k0 + s * BK,
                               Asm + s * BM * RS, Bsm + s * BN * RS, tid);
        else asm volatile("cp.async.commit_group;");
    }

    for (int i = 0; i < nk; i++) {
        asm volatile("cp.async.wait_group %0;" :: "n"(STG - 2));
        __syncthreads();

        int nt_tile = i + STG - 1;
        if (nt_tile < nk) {
            int slot = nt_tile % STG;
            issue_tile(A, lda, Bm, ldb, bm, bn, N, k0 + nt_tile * BK,
                       Asm + slot * BM * RS, Bsm + slot * BN * RS, tid);
        } else {
            asm volatile("cp.async.commit_group;");
        }

        const uint32_t* aw = (const uint32_t*)(Asm + (i % STG) * BM * RS);
        const uint32_t* bw = (const uint32_t*)(Bsm + (i % STG) * BN * RS);

#pragma unroll
        for (int ks = 0; ks < 4; ks++) {
            uint32_t af[2][4], bf[4][2];
            const int c = ks * 8 + (lane & 3);
#pragma unroll
            for (int mt = 0; mt < 2; mt++) {
                int r = wm * 32 + mt * 16 + (lane >> 2);
                af[mt][0] = aw[r * 36 + c];
                af[mt][1] = aw[(r + 8) * 36 + c];
                af[mt][2] = aw[r * 36 + c + 4];
                af[mt][3] = aw[(r + 8) * 36 + c + 4];
            }
#pragma unroll
            for (int nt = 0; nt < 4; nt++) {
                int n = wn * 32 + nt * 8 + (lane >> 2);
                bf[nt][0] = bw[n * 36 + c];
                bf[nt][1] = bw[n * 36 + c + 4];
            }
#pragma unroll
            for (int mt = 0; mt < 2; mt++)
#pragma unroll
                for (int nt = 0; nt < 4; nt++)
                    asm volatile(
                        "mma.sync.aligned.m16n8k16.row.col.f32.f16.f16.f32 "
                        "{%0,%1,%2,%3}, {%4,%5,%6,%7}, {%8,%9}, {%0,%1,%2,%3};"
                        : "+f"(acc[mt][nt][0]), "+f"(acc[mt][nt][1]),
                          "+f"(acc[mt][nt][2]), "+f"(acc[mt][nt][3])
                        : "r"(af[mt][0]), "r"(af[mt][1]), "r"(af[mt][2]), "r"(af[mt][3]),
                          "r"(bf[nt][0]), "r"(bf[nt][1]));
        }
    }

    // epilogue
    float* Cz = Cf + (size_t)z * partStride;
#pragma unroll
    for (int mt = 0; mt < 2; mt++) {
        int r0 = bm + wm * 32 + mt * 16 + (lane >> 2);
#pragma unroll
        for (int nt = 0; nt < 4; nt++) {
            int cg = bn + wn * 32 + nt * 8 + (lane & 3) * 2;
            float bv0 = 0.f, bv1 = 0.f;
            if (bias) {
                if (cg < N) bv0 = bias[cg];
                if (cg + 1 < N) bv1 = bias[cg + 1];
            }
            float v00 = acc[mt][nt][0] + bv0, v01 = acc[mt][nt][1] + bv1;
            float v10 = acc[mt][nt][2] + bv0, v11 = acc[mt][nt][3] + bv1;
            if (Ch) {
                if (cg < N) {
                    Ch[(size_t)r0 * ldc + cg]       = __float2half(v00);
                    Ch[(size_t)(r0 + 8) * ldc + cg] = __float2half(v10);
                }
                if (cg + 1 < N) {
                    Ch[(size_t)r0 * ldc + cg + 1]       = __float2half(v01);
                    Ch[(size_t)(r0 + 8) * ldc + cg + 1] = __float2half(v11);
                }
            } else {
                if (cg < N) {
                    Cz[(size_t)r0 * ldc + cg]       = v00;
                    Cz[(size_t)(r0 + 8) * ldc + cg] = v10;
                }
                if (cg + 1 < N) {
                    Cz[(size_t)r0 * ldc + cg + 1]       = v01;
                    Cz[(size_t)(r0 + 8) * ldc + cg + 1] = v11;
                }
            }
        }
    }
}

// ---------------- attention + gin assembly (one block per batch b) ---------
__global__ void __launch_bounds__(256)
attn_kernel(const int* __restrict__ captions,
            const float* __restrict__ b_datt,
            const float* __restrict__ W_fatt,
            const float* __restrict__ b_fatt,
            const __half* __restrict__ hprev,
            int t)
{
    int b = blockIdx.x;
    int tid = threadIdx.x;
    int warp = tid >> 5, lane = tid & 31;

    __shared__ float att2s[A_];
    __shared__ float es[P_];

    for (int a = tid; a < A_; a += 256) {
        float s = b_datt[a];
#pragma unroll
        for (int zz = 0; zz < 8; zz++) s += g_att2p[zz * B_ * A_ + b * A_ + a];
        att2s[a] = s;
    }
    __syncthreads();

    const float* att1b = g_att1 + (size_t)b * P_ * A_;
    for (int p = warp; p < P_; p += 8) {
        float s = 0.f;
        for (int a = lane; a < A_; a += 32) {
            float v = att1b[p * A_ + a] + att2s[a];
            s += fmaxf(v, 0.f) * W_fatt[a];
        }
#pragma unroll
        for (int o = 16; o; o >>= 1) s += __shfl_xor_sync(0xffffffffu, s, o);
        if (lane == 0) es[p] = s + b_fatt[0];
    }
    __syncthreads();

    if (warp == 0) {
        float v0 = (lane < P_) ? es[lane] : -1e30f;
        float v1 = (lane + 32 < P_) ? es[lane + 32] : -1e30f;
        float m = fmaxf(v0, v1);
#pragma unroll
        for (int o = 16; o; o >>= 1) m = fmaxf(m, __shfl_xor_sync(0xffffffffu, m, o));
        float e0 = (lane < P_) ? __expf(v0 - m) : 0.f;
        float e1 = (lane + 32 < P_) ? __expf(v1 - m) : 0.f;
        float s = e0 + e1;
#pragma unroll
        for (int o = 16; o; o >>= 1) s += __shfl_xor_sync(0xffffffffu, s, o);
        float inv = 1.0f / s;
        if (lane < P_) es[lane] = e0 * inv;
        if (lane + 32 < P_) es[lane + 32] = e1 * inv;
    }
    __syncthreads();

    __half* gin = g_gin + (size_t)b * GK_;
    int cap = captions[b * T_ + t];
    const __half* erow = g_embh + (size_t)cap * E_;
    for (int i = tid; i < E_; i += 256) gin[i] = erow[i];

    const __half* encb = g_ench + (size_t)b * P_ * ENC_;
    for (int e = tid; e < ENC_; e += 256) {
        float s = 0.f;
#pragma unroll 7
        for (int p = 0; p < P_; p++) s += es[p] * __half2float(encb[p * ENC_ + e]);
        gin[E_ + e] = __float2half(s);
    }
    for (int j = tid; j < H_; j += 256) gin[K1_ + j] = hprev[b * H_ + j];
}

// ---------------- LSTM pointwise (reduces gates split-K partials) ----------
__global__ void __launch_bounds__(256)
lstm_kernel(const float* __restrict__ b_ih, const float* __restrict__ b_hh,
            const float* __restrict__ cprev,
            __half* __restrict__ hnew, float* __restrict__ cnew)
{
    int i = blockIdx.x * blockDim.x + threadIdx.x;
    if (i >= B_ * H_) return;
    int b = i >> 10, j = i & (H_ - 1);
    size_t base = (size_t)b * 4 * H_ + j;
    float gi = 0.f, gf = 0.f, gg = 0.f, go = 0.f;
#pragma unroll
    for (int zz = 0; zz < 2; zz++) {
        const float* gp = g_gatesp + (size_t)zz * B_ * 4 * H_ + base;
        gi += gp[0]; gf += gp[H_]; gg += gp[2 * H_]; go += gp[3 * H_];
    }
    gi += b_ih[j]          + b_hh[j];
    gf += b_ih[H_ + j]     + b_hh[H_ + j];
    gg += b_ih[2 * H_ + j] + b_hh[2 * H_ + j];
    go += b_ih[3 * H_ + j] + b_hh[3 * H_ + j];
    float si = 1.f / (1.f + __expf(-gi));
    float sf = 1.f / (1.f + __expf(-gf));
    float so = 1.f / (1.f + __expf(-go));
    float tg = tanhf(gg);
    float c  = sf * cprev[i] + si * tg;
    cnew[i] = c;
    hnew[i] = __float2half(so * tanhf(c));
}

// ---------------- host ----------------
template <typename T>
static T* sym_addr(const void* sym) {
    void* p = nullptr;
    cudaGetSymbolAddress(&p, sym);
    return (T*)p;
}

extern "C" void kernel_launch(void* const* d_in, const int* in_sizes, int n_in,
                              void* d_out, int out_size)
{
    const float* enc    = (const float*)d_in[0];
    const int*   caps   = (const int*)  d_in[1];
    const float* embed  = (const float*)d_in[2];
    const float* W_eatt = (const float*)d_in[3];
    const float* b_eatt = (const float*)d_in[4];
    const float* W_datt = (const float*)d_in[5];
    const float* b_datt = (const float*)d_in[6];
    const float* W_fatt = (const float*)d_in[7];
    const float* b_fatt = (const float*)d_in[8];
    const float* W_ih   = (const float*)d_in[9];
    const float* b_ih   = (const float*)d_in[10];
    const float* W_hh   = (const float*)d_in[11];
    const float* b_hh   = (const float*)d_in[12];
    const float* W_h0   = (const float*)d_in[13];
    const float* b_h0   = (const float*)d_in[14];
    const float* W_c0   = (const float*)d_in[15];
    const float* b_c0   = (const float*)d_in[16];
    const float* W_out  = (const float*)d_in[17];
    const float* b_out  = (const float*)d_in[18];
    float* out = (float*)d_out;

    static bool attr_set = false;
    if (!attr_set) {
        cudaFuncSetAttribute(hgemm, cudaFuncAttributeMaxDynamicSharedMemorySize, SMEM_BYTES);
        attr_set = true;
    }

    __half* Wouth = sym_addr<__half>(g_Wout);
    __half* Wgh   = sym_addr<__half>(g_Wg);
    __half* Wdth  = sym_addr<__half>(g_Wdatt);
    __half* Weth  = sym_addr<__half>(g_Weatt);
    __half* Wh0h  = sym_addr<__half>(g_Wh0);
    __half* Wc0h  = sym_addr<__half>(g_Wc0);
    __half* ench  = sym_addr<__half>(g_ench);
    __half* meanh = sym_addr<__half>(g_meanh);
    __half* hbuf  = sym_addr<__half>(g_hbuf);
    __half* gin   = sym_addr<__half>(g_gin);
    float*  cbuf  = sym_addr<float>(g_cbuf);
    float*  att1  = sym_addr<float>(g_att1);
    float*  att2p = sym_addr<float>(g_att2p);
    float*  gatesp= sym_addr<float>(g_gatesp);

    const int BH = B_ * H_;

    // setup
    mean_kernel<<<(B_ * ENC_ + 255) / 256, 256>>>(enc);
    cvt_all<<<(S8 + 255) / 256, 256>>>(W_datt, W_out, W_eatt, W_h0, W_c0, enc, embed, W_ih, W_hh);
    // h0 (half out), c0 (fp32 out)
    hgemm<<<dim3(1, H_ / 64, 1), 128, SMEM_BYTES>>>(meanh, ENC_, Wh0h, ENC_, b_h0,
                                                    nullptr, hbuf, H_, 0, H_, ENC_);
    hgemm<<<dim3(1, H_ / 64, 1), 128, SMEM_BYTES>>>(meanh, ENC_, Wc0h, ENC_, b_c0,
                                                    cbuf, nullptr, H_, 0, H_, ENC_);
    // att1 = enc @ W_eatt^T + b_eatt   [3136 x 512], K=1280
    hgemm<<<dim3((B_ * P_) / 64, A_ / 64, 1), 128, SMEM_BYTES>>>(ench, ENC_, Weth, ENC_, b_eatt,
                                                                 att1, nullptr, A_, 0, A_, ENC_);

    for (int t = 0; t < T_ - 1; t++) {
        __half* h_cur = hbuf + (t & 1) * BH;
        float*  c_cur = cbuf + (t & 1) * BH;
        __half* h_nxt = hbuf + ((t + 1) & 1) * BH;
        float*  c_nxt = cbuf + ((t + 1) & 1) * BH;

        // att2 partials: h @ W_datt^T, split-K 8 (64 blocks)
        hgemm<<<dim3(1, A_ / 64, 8), 128, SMEM_BYTES>>>(h_cur, H_, Wdth, H_, nullptr,
                                                        att2p, nullptr, A_, B_ * A_, A_, H_ / 8);

        // attention + gin = [x_t | ctx | h]
        attn_kernel<<<B_, 256>>>(caps, b_datt, W_fatt, b_fatt, h_cur, t);

        // gates partials: gin @ Wg^T, split-K 2 (128 blocks)
        hgemm<<<dim3(1, (4 * H_) / 64, 2), 128, SMEM_BYTES>>>(gin, GK_, Wgh, GK_, nullptr,
                                                              gatesp, nullptr, 4 * H_,
                                                              B_ * 4 * H_, 4 * H_, GK_ / 2);

        // LSTM pointwise
        lstm_kernel<<<(B_ * H_ + 255) / 256, 256>>>(b_ih, b_hh, c_cur, h_nxt, c_nxt);

        // logits: h_new @ W_out^T + b_out -> out[:, t, :]
        hgemm<<<dim3(1, (V_ + 63) / 64, 1), 128, SMEM_BYTES>>>(h_nxt, H_, Wouth, H_, b_out,
                                                               out + (size_t)t * V_, nullptr,
                                                               (T_ - 1) * V_, 0, V_, H_);
    }
}

// round 3
// speedup vs baseline: 2.0569x; 1.0223x over previous
#include <cuda_runtime.h>
#include <cuda_fp16.h>
#include <cstdint>

#define B_    64
#define P_    49
#define ENC_  1280
#define T_    25
#define V_    10000
#define E_    512
#define H_    1024
#define A_    512
#define GK_   2816   /* E + ENC + H */
#define K1_   1792   /* E + ENC */

#define BM 64
#define BN 64
#define BK 64
#define STG 5
#define RS 72        /* smem row stride in halves (64 + 8 pad) */
#define SMEM_BYTES (STG * (BM + BN) * RS * 2)

#define NLOGIT ((V_ + 63) / 64)   /* 157 */

// ---------------- static scratch (no allocs) ----------------
__device__ __align__(16) __half g_Wout [V_ * H_];
__device__ __align__(16) __half g_Wg   [4 * H_ * GK_];
__device__ __align__(16) __half g_Wdatt[A_ * H_];
__device__ __align__(16) __half g_Weatt[A_ * ENC_];
__device__ __align__(16) __half g_Wh0  [H_ * ENC_];
__device__ __align__(16) __half g_Wc0  [H_ * ENC_];
__device__ __align__(16) __half g_ench [B_ * P_ * ENC_];
__device__ __align__(16) __half g_meanh[B_ * ENC_];
__device__ __align__(16) __half g_hbuf [2 * B_ * H_];
__device__ __align__(16) __half g_gin  [B_ * GK_];
__device__ __align__(16) float  g_cbuf [2 * B_ * H_];
__device__ __align__(16) float  g_att1 [B_ * P_ * A_];
__device__ __align__(16) float  g_att2p[8 * B_ * A_];
__device__ __align__(16) float  g_gatesp[4 * B_ * 4 * H_];

// ---------------- setup: convert to fp16 ----------------
#define S0 (A_ * H_)                    /* W_datt */
#define S1 (S0 + V_ * H_)               /* W_out  */
#define S2 (S1 + A_ * ENC_)             /* W_eatt */
#define S3 (S2 + H_ * ENC_)             /* W_h0   */
#define S4 (S3 + H_ * ENC_)             /* W_c0   */
#define S5 (S4 + B_ * P_ * ENC_)        /* enc    */
#define S6 (S5 + 4 * H_ * K1_)          /* W_ih -> Wg[:, :1792] */
#define S7 (S6 + 4 * H_ * H_)           /* W_hh -> Wg[:, 1792:] */

__global__ void cvt_all(const float* __restrict__ Wd, const float* __restrict__ Wo,
                        const float* __restrict__ We, const float* __restrict__ Wh0,
                        const float* __restrict__ Wc0, const float* __restrict__ enc,
                        const float* __restrict__ Wih, const float* __restrict__ Whh)
{
    int i = blockIdx.x * 256 + threadIdx.x;
    if (i >= S7) return;
    if (i < S0)      g_Wdatt[i]      = __float2half(Wd[i]);
    else if (i < S1) g_Wout[i - S0]  = __float2half(Wo[i - S0]);
    else if (i < S2) g_Weatt[i - S1] = __float2half(We[i - S1]);
    else if (i < S3) g_Wh0[i - S2]   = __float2half(Wh0[i - S2]);
    else if (i < S4) g_Wc0[i - S3]   = __float2half(Wc0[i - S3]);
    else if (i < S5) g_ench[i - S4]  = __float2half(enc[i - S4]);
    else if (i < S6) {
        int j = i - S5; int r = j / K1_, c = j % K1_;
        g_Wg[(size_t)r * GK_ + c] = __float2half(Wih[j]);
    } else {
        int j = i - S6; int r = j / H_, c = j % H_;
        g_Wg[(size_t)r * GK_ + K1_ + c] = __float2half(Whh[j]);
    }
}

__global__ void mean_kernel(const float* __restrict__ enc) {
    int i = blockIdx.x * blockDim.x + threadIdx.x;
    if (i >= B_ * ENC_) return;
    int b = i / ENC_, e = i % ENC_;
    const float* p = enc + (size_t)b * P_ * ENC_ + e;
    float s = 0.f;
#pragma unroll 7
    for (int k = 0; k < P_; k++) s += p[k * ENC_];
    g_meanh[i] = __float2half(s * (1.0f / P_));
}

// ---------------- fp16 GEMM core: C[M,N] = A[M,K] @ B[N,K]^T (+bias) ------
__device__ __forceinline__ void issue_tile(
    const __half* __restrict__ A, int lda,
    const __half* __restrict__ B, int ldb,
    int bm, int bn, int N, int kt,
    __half* as, __half* bs, int tid)
{
#pragma unroll
    for (int i = 0; i < 4; i++) {
        int idx = i * 128 + tid;
        int r = idx >> 3, c8 = (idx & 7) * 8;
        uint32_t da = (uint32_t)__cvta_generic_to_shared(as + r * RS + c8);
        const __half* pa = A + (size_t)(bm + r) * lda + kt + c8;
        asm volatile("cp.async.cg.shared.global [%0], [%1], 16;" :: "r"(da), "l"(pa));
        int n = bn + r;
        uint32_t db = (uint32_t)__cvta_generic_to_shared(bs + r * RS + c8);
        const __half* pb = B + (size_t)(n < N ? n : 0) * ldb + kt + c8;
        int sz = (n < N) ? 16 : 0;
        asm volatile("cp.async.cg.shared.global [%0], [%1], 16, %2;" :: "r"(db), "l"(pb), "r"(sz));
    }
    asm volatile("cp.async.commit_group;");
}

__device__ __forceinline__ void gemm_core(
    const __half* __restrict__ A, int lda,
    const __half* __restrict__ Bm, int ldb,
    const float* __restrict__ bias,
    float* __restrict__ Cf, __half* __restrict__ Ch,
    int ldc, int partStride, int N, int kChunk,
    int bm, int by, int z)
{
    extern __shared__ __half sm[];
    __half* Asm = sm;
    __half* Bsm = sm + STG * BM * RS;

    const int tid = threadIdx.x;
    const int warp = tid >> 5, lane = tid & 31;
    const int wm = warp >> 1, wn = warp & 1;
    const int bn = by * BN;
    const int k0 = z * kChunk;
    const int nk = kChunk / BK;

    float acc[2][4][4];
#pragma unroll
    for (int i = 0; i < 2; i++)
#pragma unroll
        for (int j = 0; j < 4; j++)
#pragma unroll
            for (int q = 0; q < 4; q++) acc[i][j][q] = 0.f;

#pragma unroll
    for (int s = 0; s < STG - 1; s++) {
        if (s < nk) issue_tile(A, lda, Bm, ldb, bm, bn, N, k0 + s * BK,
                               Asm + s * BM * RS, Bsm + s * BN * RS, tid);
        else asm volatile("cp.async.commit_group;");
    }

    for (int i = 0; i < nk; i++) {
        asm volatile("cp.async.wait_group %0;" :: "n"(STG - 2));
        __syncthreads();

        int ntile = i + STG - 1;
        if (ntile < nk) {
            int slot = ntile % STG;
            issue_tile(A, lda, Bm, ldb, bm, bn, N, k0 + ntile * BK,
                       Asm + slot * BM * RS, Bsm + slot * BN * RS, tid);
        } else {
            asm volatile("cp.async.commit_group;");
        }

        const uint32_t* aw = (const uint32_t*)(Asm + (i % STG) * BM * RS);
        const uint32_t* bw = (const uint32_t*)(Bsm + (i % STG) * BN * RS);

#pragma unroll
        for (int ks = 0; ks < 4; ks++) {
            uint32_t af[2][4], bf[4][2];
            const int c = ks * 8 + (lane & 3);
#pragma unroll
            for (int mt = 0; mt < 2; mt++) {
                int r = wm * 32 + mt * 16 + (lane >> 2);
                af[mt][0] = aw[r * 36 + c];
                af[mt][1] = aw[(r + 8) * 36 + c];
                af[mt][2] = aw[r * 36 + c + 4];
                af[mt][3] = aw[(r + 8) * 36 + c + 4];
            }
#pragma unroll
            for (int nt = 0; nt < 4; nt++) {
                int n = wn * 32 + nt * 8 + (lane >> 2);
                bf[nt][0] = bw[n * 36 + c];
                bf[nt][1] = bw[n * 36 + c + 4];
            }
#pragma unroll
            for (int mt = 0; mt < 2; mt++)
#pragma unroll
                for (int nt = 0; nt < 4; nt++)
                    asm volatile(
                        "mma.sync.aligned.m16n8k16.row.col.f32.f16.f16.f32 "
                        "{%0,%1,%2,%3}, {%4,%5,%6,%7}, {%8,%9}, {%0,%1,%2,%3};"
                        : "+f"(acc[mt][nt][0]), "+f"(acc[mt][nt][1]),
                          "+f"(acc[mt][nt][2]), "+f"(acc[mt][nt][3])
                        : "r"(af[mt][0]), "r"(af[mt][1]), "r"(af[mt][2]), "r"(af[mt][3]),
                          "r"(bf[nt][0]), "r"(bf[nt][1]));
        }
    }

    float* Cz = Cf + (size_t)z * partStride;
#pragma unroll
    for (int mt = 0; mt < 2; mt++) {
        int r0 = bm + wm * 32 + mt * 16 + (lane >> 2);
#pragma unroll
        for (int nt = 0; nt < 4; nt++) {
            int cg = bn + wn * 32 + nt * 8 + (lane & 3) * 2;
            float bv0 = 0.f, bv1 = 0.f;
            if (bias) {
                if (cg < N) bv0 = bias[cg];
                if (cg + 1 < N) bv1 = bias[cg + 1];
            }
            float v00 = acc[mt][nt][0] + bv0, v01 = acc[mt][nt][1] + bv1;
            float v10 = acc[mt][nt][2] + bv0, v11 = acc[mt][nt][3] + bv1;
            if (Ch) {
                if (cg < N) {
                    Ch[(size_t)r0 * ldc + cg]       = __float2half(v00);
                    Ch[(size_t)(r0 + 8) * ldc + cg] = __float2half(v10);
                }
                if (cg + 1 < N) {
                    Ch[(size_t)r0 * ldc + cg + 1]       = __float2half(v01);
                    Ch[(size_t)(r0 + 8) * ldc + cg + 1] = __float2half(v11);
                }
            } else {
                if (cg < N) {
                    Cz[(size_t)r0 * ldc + cg]       = v00;
                    Cz[(size_t)(r0 + 8) * ldc + cg] = v10;
                }
                if (cg + 1 < N) {
                    Cz[(size_t)r0 * ldc + cg + 1]       = v01;
                    Cz[(size_t)(r0 + 8) * ldc + cg + 1] = v11;
                }
            }
        }
    }
}

__global__ void __launch_bounds__(128)
hgemm(const __half* __restrict__ A, int lda,
      const __half* __restrict__ Bm, int ldb,
      const float* __restrict__ bias,
      float* __restrict__ Cf, __half* __restrict__ Ch,
      int ldc, int partStride, int N, int kChunk)
{
    gemm_core(A, lda, Bm, ldb, bias, Cf, Ch, ldc, partStride, N, kChunk,
              blockIdx.x * BM, blockIdx.y, blockIdx.z);
}

// combo: logits(t) [157 blocks] + att2(t+1) split-K8 [64 blocks]; same A = h_new
__global__ void __launch_bounds__(128)
combo_kernel(const __half* __restrict__ h,
             const float* __restrict__ b_out,
             float* __restrict__ outT)
{
    int bi = blockIdx.x;
    if (bi < NLOGIT) {
        gemm_core(h, H_, g_Wout, H_, b_out, outT, nullptr,
                  (T_ - 1) * V_, 0, V_, H_, 0, bi, 0);
    } else {
        int i = bi - NLOGIT;
        gemm_core(h, H_, g_Wdatt, H_, nullptr, g_att2p, nullptr,
                  A_, B_ * A_, A_, H_ / 8, 0, i & 7, i >> 3);
    }
}

// ---------------- attention + gin assembly (one block per batch b) ---------
__global__ void __launch_bounds__(256)
attn_kernel(const int* __restrict__ captions,
            const float* __restrict__ embed,
            const float* __restrict__ b_datt,
            const float* __restrict__ W_fatt,
            const float* __restrict__ b_fatt,
            const __half* __restrict__ hprev,
            int t)
{
    int b = blockIdx.x;
    int tid = threadIdx.x;
    int warp = tid >> 5, lane = tid & 31;

    __shared__ float att2s[A_];
    __shared__ float es[P_];

    for (int a = tid; a < A_; a += 256) {
        float s = b_datt[a];
#pragma unroll
        for (int zz = 0; zz < 8; zz++) s += g_att2p[zz * B_ * A_ + b * A_ + a];
        att2s[a] = s;
    }
    __syncthreads();

    const float* att1b = g_att1 + (size_t)b * P_ * A_;
    for (int p = warp; p < P_; p += 8) {
        float s = 0.f;
        for (int a = lane; a < A_; a += 32) {
            float v = att1b[p * A_ + a] + att2s[a];
            s += fmaxf(v, 0.f) * W_fatt[a];
        }
#pragma unroll
        for (int o = 16; o; o >>= 1) s += __shfl_xor_sync(0xffffffffu, s, o);
        if (lane == 0) es[p] = s + b_fatt[0];
    }
    __syncthreads();

    if (warp == 0) {
        float v0 = (lane < P_) ? es[lane] : -1e30f;
        float v1 = (lane + 32 < P_) ? es[lane + 32] : -1e30f;
        float m = fmaxf(v0, v1);
#pragma unroll
        for (int o = 16; o; o >>= 1) m = fmaxf(m, __shfl_xor_sync(0xffffffffu, m, o));
        float e0 = (lane < P_) ? __expf(v0 - m) : 0.f;
        float e1 = (lane + 32 < P_) ? __expf(v1 - m) : 0.f;
        float s = e0 + e1;
#pragma unroll
        for (int o = 16; o; o >>= 1) s += __shfl_xor_sync(0xffffffffu, s, o);
        float inv = 1.0f / s;
        if (lane < P_) es[lane] = e0 * inv;
        if (lane + 32 < P_) es[lane + 32] = e1 * inv;
    }
    __syncthreads();

    __half* gin = g_gin + (size_t)b * GK_;
    int cap = captions[b * T_ + t];
    const float* erow = embed + (size_t)cap * E_;
    for (int i = tid; i < E_; i += 256) gin[i] = __float2half(erow[i]);

    const __half* encb = g_ench + (size_t)b * P_ * ENC_;
    for (int e = tid; e < ENC_; e += 256) {
        float s = 0.f;
#pragma unroll 7
        for (int p = 0; p < P_; p++) s += es[p] * __half2float(encb[p * ENC_ + e]);
        gin[E_ + e] = __float2half(s);
    }
    for (int j = tid; j < H_; j += 256) gin[K1_ + j] = hprev[b * H_ + j];
}

// ---------------- LSTM pointwise (reduces 4 gates partials) ----------------
__global__ void __launch_bounds__(256)
lstm_kernel(const float* __restrict__ b_ih, const float* __restrict__ b_hh,
            const float* __restrict__ cprev,
            __half* __restrict__ hnew, float* __restrict__ cnew)
{
    int i = blockIdx.x * blockDim.x + threadIdx.x;
    if (i >= B_ * H_) return;
    int b = i >> 10, j = i & (H_ - 1);
    size_t base = (size_t)b * 4 * H_ + j;
    float gi = 0.f, gf = 0.f, gg = 0.f, go = 0.f;
#pragma unroll
    for (int zz = 0; zz < 4; zz++) {
        const float* gp = g_gatesp + (size_t)zz * B_ * 4 * H_ + base;
        gi += gp[0]; gf += gp[H_]; gg += gp[2 * H_]; go += gp[3 * H_];
    }
    gi += b_ih[j]          + b_hh[j];
    gf += b_ih[H_ + j]     + b_hh[H_ + j];
    gg += b_ih[2 * H_ + j] + b_hh[2 * H_ + j];
    go += b_ih[3 * H_ + j] + b_hh[3 * H_ + j];
    float si = 1.f / (1.f + __expf(-gi));
    float sf = 1.f / (1.f + __expf(-gf));
    float so = 1.f / (1.f + __expf(-go));
    float tg = tanhf(gg);
    float c  = sf * cprev[i] + si * tg;
    cnew[i] = c;
    hnew[i] = __float2half(so * tanhf(c));
}

// ---------------- host ----------------
template <typename T>
static T* sym_addr(const void* sym) {
    void* p = nullptr;
    cudaGetSymbolAddress(&p, sym);
    return (T*)p;
}

extern "C" void kernel_launch(void* const* d_in, const int* in_sizes, int n_in,
                              void* d_out, int out_size)
{
    const float* enc    = (const float*)d_in[0];
    const int*   caps   = (const int*)  d_in[1];
    const float* embed  = (const float*)d_in[2];
    const float* W_eatt = (const float*)d_in[3];
    const float* b_eatt = (const float*)d_in[4];
    const float* W_datt = (const float*)d_in[5];
    const float* b_datt = (const float*)d_in[6];
    const float* W_fatt = (const float*)d_in[7];
    const float* b_fatt = (const float*)d_in[8];
    const float* W_ih   = (const float*)d_in[9];
    const float* b_ih   = (const float*)d_in[10];
    const float* W_hh   = (const float*)d_in[11];
    const float* b_hh   = (const float*)d_in[12];
    const float* W_h0   = (const float*)d_in[13];
    const float* b_h0   = (const float*)d_in[14];
    const float* W_c0   = (const float*)d_in[15];
    const float* b_c0   = (const float*)d_in[16];
    const float* W_out  = (const float*)d_in[17];
    const float* b_out  = (const float*)d_in[18];
    float* out = (float*)d_out;

    cudaFuncSetAttribute(hgemm, cudaFuncAttributeMaxDynamicSharedMemorySize, SMEM_BYTES);
    cudaFuncSetAttribute(combo_kernel, cudaFuncAttributeMaxDynamicSharedMemorySize, SMEM_BYTES);

    __half* Wdth  = sym_addr<__half>(g_Wdatt);
    __half* Weth  = sym_addr<__half>(g_Weatt);
    __half* Wh0h  = sym_addr<__half>(g_Wh0);
    __half* Wc0h  = sym_addr<__half>(g_Wc0);
    __half* ench  = sym_addr<__half>(g_ench);
    __half* meanh = sym_addr<__half>(g_meanh);
    __half* hbuf  = sym_addr<__half>(g_hbuf);
    __half* gin   = sym_addr<__half>(g_gin);
    __half* Wgh   = sym_addr<__half>(g_Wg);
    float*  cbuf  = sym_addr<float>(g_cbuf);
    float*  att1  = sym_addr<float>(g_att1);
    float*  att2p = sym_addr<float>(g_att2p);
    float*  gatesp= sym_addr<float>(g_gatesp);

    const int BH = B_ * H_;

    // setup
    mean_kernel<<<(B_ * ENC_ + 255) / 256, 256>>>(enc);
    cvt_all<<<(S7 + 255) / 256, 256>>>(W_datt, W_out, W_eatt, W_h0, W_c0, enc, W_ih, W_hh);
    hgemm<<<dim3(1, H_ / 64, 1), 128, SMEM_BYTES>>>(meanh, ENC_, Wh0h, ENC_, b_h0,
                                                    nullptr, hbuf, H_, 0, H_, ENC_);
    hgemm<<<dim3(1, H_ / 64, 1), 128, SMEM_BYTES>>>(meanh, ENC_, Wc0h, ENC_, b_c0,
                                                    cbuf, nullptr, H_, 0, H_, ENC_);
    hgemm<<<dim3((B_ * P_) / 64, A_ / 64, 1), 128, SMEM_BYTES>>>(ench, ENC_, Weth, ENC_, b_eatt,
                                                                 att1, nullptr, A_, 0, A_, ENC_);
    // att2 for t=0 (split-K 8)
    hgemm<<<dim3(1, A_ / 64, 8), 128, SMEM_BYTES>>>(hbuf, H_, Wdth, H_, nullptr,
                                                    att2p, nullptr, A_, B_ * A_, A_, H_ / 8);

    for (int t = 0; t < T_ - 1; t++) {
        __half* h_cur = hbuf + (t & 1) * BH;
        float*  c_cur = cbuf + (t & 1) * BH;
        __half* h_nxt = hbuf + ((t + 1) & 1) * BH;
        float*  c_nxt = cbuf + ((t + 1) & 1) * BH;

        // attention + gin = [x_t | ctx | h]  (consumes att2p from previous combo)
        attn_kernel<<<B_, 256>>>(caps, embed, b_datt, W_fatt, b_fatt, h_cur, t);

        // gates partials: gin @ Wg^T, split-K 4 (grid 256)
        hgemm<<<dim3(1, (4 * H_) / 64, 4), 128, SMEM_BYTES>>>(gin, GK_, Wgh, GK_, nullptr,
                                                              gatesp, nullptr, 4 * H_,
                                                              B_ * 4 * H_, 4 * H_, GK_ / 4);

        // LSTM pointwise
        lstm_kernel<<<(B_ * H_ + 255) / 256, 256>>>(b_ih, b_hh, c_cur, h_nxt, c_nxt);

        // logits(t) + att2(t+1) fused (221 blocks)
        combo_kernel<<<NLOGIT + 64, 128, SMEM_BYTES>>>(h_nxt, b_out, out + (size_t)t * V_);
    }
}